// round 16
// baseline (speedup 1.0000x reference)
#include <cuda_runtime.h>
#include <cstdint>

#define BB 16
#define NN 577
#define HH 12
#define TQ 64
#define NT 512
#define XS 2304          // x row stride (floats)
#define OS 768           // out row stride (floats)
#define SDIM 608         // padded key dim
#define SS 612           // S/p row stride; 612 mod 32 = 4 -> conflict-free A-frag LDS
#define QSS 68           // Q smem stride; 68 mod 32 = 4 -> conflict-free frag LDS
#define KSS 68           // K tile stride (Phase B)
#define VSS 72           // V tile stride; 72 mod 32 = 8 -> conflict-free B-frag LDS
#define SCALEF 0.125f

// ---- shared memory map (floats) ----
#define OFF_S    0                     // 64*612 = 39168 (scores -> p in place)
#define OFF_KS   39168                 // K[128][68]=8704 / V[128][72]=9216 / TK / PART overlay
#define OFF_QS   (OFF_KS + 9216)       // 48384, Q [64][68] fp32 scaled
#define OFF_BV   (OFF_QS + 64*QSS)     // 52736, [n][24]
#define OFF_BH   (OFF_BV + 64*24)      // 54272, [n][24]
#define OFF_B0   (OFF_BH + 64*24)      // 55808
#define OFF_P0   (OFF_B0 + 64)         // 55872
#define OFF_INV  (OFF_P0 + 64)         // 55936
#define SMEM_FLOATS (OFF_INV + 64)     // 56000 floats = 224,000 B (< 227KB opt-in)

#define OFF_TK   OFF_KS                // rel_k tables [60][68] -- dead after A2
#define OFF_VT   OFF_KS
#define OFF_PART OFF_KS                // O staging [64][64] after Phase E
#define OFF_RS   OFF_BV                // Phase D reuse
#define OFF_CS   OFF_BH

__device__ __forceinline__ int clip14(int v) {
    v = v < -14 ? -14 : (v > 14 ? 14 : v);
    return v + 15;
}
__device__ __forceinline__ uint32_t cvt_tf32(float f) {
    uint32_t r; asm("cvt.rna.tf32.f32 %0, %1;" : "=r"(r) : "f"(f)); return r;
}
__device__ __forceinline__ void split_tf32(float f, uint32_t& h, uint32_t& l) {
    h = cvt_tf32(f);
    l = cvt_tf32(f - __uint_as_float(h));
}
__device__ __forceinline__ void mma_tf32(float* c, uint32_t a0, uint32_t a1, uint32_t a2,
                                         uint32_t a3, uint32_t b0, uint32_t b1) {
    asm volatile(
        "mma.sync.aligned.m16n8k8.row.col.f32.tf32.tf32.f32 "
        "{%0,%1,%2,%3},{%4,%5,%6,%7},{%8,%9},{%0,%1,%2,%3};"
        : "+f"(c[0]), "+f"(c[1]), "+f"(c[2]), "+f"(c[3])
        : "r"(a0), "r"(a1), "r"(a2), "r"(a3), "r"(b0), "r"(b1));
}
#define DOT4(A, Q, K) { A += Q.x*K.x; A += Q.y*K.y; A += Q.z*K.z; A += Q.w*K.w; }

__global__ __launch_bounds__(NT, 1)
void attn_kernel(const float* __restrict__ x, const float* __restrict__ wts,
                 const float* __restrict__ tkv, const float* __restrict__ tkh,
                 const float* __restrict__ tvv, const float* __restrict__ tvh,
                 float* __restrict__ out)
{
    extern __shared__ float sm[];
    const int tid = threadIdx.x;
    const int wid = tid >> 5, lane = tid & 31;
    const int qt = blockIdx.x, h = blockIdx.y, b = blockIdx.z;
    const int n0 = qt * TQ;
    const int rowblk = wid & 3, colblk = wid >> 2;
    const int R0 = rowblk * 16;
    const int ly = lane >> 2, lx = lane & 3;      // frag lane decomposition

    float w = __ldg(&wts[2]);
    if (h < 10) w += __ldg(&wts[1]);
    if (h < 8)  w += __ldg(&wts[0]);

    // ---------------- A1: Q -> QS[n][d] (scaled); rel_k tables -> TK scratch
    for (int idx = tid; idx < TQ * 16; idx += NT) {
        int n = idx >> 4, d4 = idx & 15;
        int qn = n0 + n;
        float4 f = make_float4(0.f, 0.f, 0.f, 0.f);
        if (qn < NN)
            f = *(const float4*)&x[((size_t)(b * NN + qn)) * XS + h * 64 + d4 * 4];
        *(float4*)&sm[OFF_QS + n * QSS + d4 * 4] =
            make_float4(f.x * w, f.y * w, f.z * w, f.w * w);
    }
    for (int idx = tid; idx < 960; idx += NT) {
        int which = (idx >= 480) ? 1 : 0;
        int i2 = idx - which * 480;
        int t = i2 >> 4, d4 = i2 & 15;
        const float* src = which ? tkh : tkv;
        float4 f = *(const float4*)&src[t * 64 + d4 * 4];
        *(float4*)&sm[OFF_TK + which * 30 * QSS + t * QSS + d4 * 4] = f;
    }
    __syncthreads();

    // ---------------- A2: per-row rel-k bias coefficients (b0, bv[24], bh[24])
    {
        int n = tid >> 3, l = tid & 7;
        int qn = n0 + n;
        bool zi = (qn == 0) || (qn >= NN);
        int gq = 0, cq = 0;
        if (!zi) { gq = (qn - 1) / 24; cq = (qn - 1) % 24; }
        const float4* qrow = (const float4*)&sm[OFF_QS + n * QSS];
        const float* skv = &sm[OFF_TK];
        const float* skh = &sm[OFF_TK + 30 * QSS];
        for (int jj = l; jj < 49; jj += 8) {
            float s = 0.f;
            if (jj == 0) {
                const float4* t0p = (const float4*)skv;
                const float4* t1p = (const float4*)skh;
                #pragma unroll 4
                for (int d4 = 0; d4 < 16; d4++) {
                    float4 q = qrow[d4], a = t0p[d4], c = t1p[d4];
                    s += q.x*(a.x+c.x) + q.y*(a.y+c.y) + q.z*(a.z+c.z) + q.w*(a.w+c.w);
                }
                sm[OFF_B0 + n] = s;
            } else if (jj <= 24) {
                int g = jj - 1;
                int t = zi ? 0 : clip14(g - gq);
                const float4* tr = (const float4*)&skv[t * QSS];
                #pragma unroll 4
                for (int d4 = 0; d4 < 16; d4++) { float4 q = qrow[d4], a = tr[d4]; DOT4(s, q, a); }
                sm[OFF_BV + n * 24 + g] = s;
            } else {
                int c = jj - 25;
                int t = zi ? 0 : clip14(c - cq);
                const float4* tr = (const float4*)&skh[t * QSS];
                #pragma unroll 4
                for (int d4 = 0; d4 < 16; d4++) { float4 q = qrow[d4], a = tr[d4]; DOT4(s, q, a); }
                sm[OFF_BH + n * 24 + c] = s;
            }
        }
    }

    // ---------------- Phase B: S = bias + Q K^T via mma.sync tf32 (hi/lo split, 3 terms)
    for (int chunk = 0; chunk < 5; chunk++) {
        __syncthreads();   // (first iter: A2's TK reads complete before KS overwrite)
        for (int idx = tid; idx < 128 * 16; idx += NT) {
            int mm = idx >> 4, d4 = idx & 15;
            int m = chunk * 128 + mm;
            float4 f = make_float4(0.f, 0.f, 0.f, 0.f);
            if (m < NN)
                f = *(const float4*)&x[((size_t)(b * NN + m)) * XS + 768 + h * 64 + d4 * 4];
            *(float4*)&sm[OFF_KS + mm * KSS + d4 * 4] =
                make_float4(f.x * w, f.y * w, f.z * w, f.w * w);
        }
        __syncthreads();

        float acc[4][4] = {{0,0,0,0},{0,0,0,0},{0,0,0,0},{0,0,0,0}};
        const float* qA = &sm[OFF_QS + (R0 + ly) * QSS + lx];
        #pragma unroll
        for (int k8 = 0; k8 < 8; k8++) {
            int kc = k8 * 8;
            uint32_t ah0, ah1, ah2, ah3, al0, al1, al2, al3;
            split_tf32(qA[kc],            ah0, al0);
            split_tf32(qA[8*QSS + kc],    ah1, al1);
            split_tf32(qA[kc + 4],        ah2, al2);
            split_tf32(qA[8*QSS + kc + 4],ah3, al3);
            #pragma unroll
            for (int nt = 0; nt < 4; nt++) {
                int nn_ = colblk * 32 + nt * 8;
                const float* bp = &sm[OFF_KS + (nn_ + ly) * KSS + kc + lx];
                uint32_t bh0, bh1, bl0, bl1;
                split_tf32(bp[0], bh0, bl0);
                split_tf32(bp[4], bh1, bl1);
                mma_tf32(acc[nt], ah0, ah1, ah2, ah3, bh0, bh1);
                mma_tf32(acc[nt], al0, al1, al2, al3, bh0, bh1);
                mma_tf32(acc[nt], ah0, ah1, ah2, ah3, bl0, bl1);
            }
        }
        // writeback with fused bias
        int mbase = chunk * 128 + colblk * 32;
        #pragma unroll
        for (int nt = 0; nt < 4; nt++) {
            int m  = mbase + nt * 8 + lx * 2;
            int m1 = m + 1;
            int gm  = (m  - 1) / 24, cm  = (m  - 1) - gm  * 24;
            int gm1 = (m1 - 1) / 24, cm1 = (m1 - 1) - gm1 * 24;
            #pragma unroll
            for (int half = 0; half < 2; half++) {
                int r = R0 + ly + half * 8;
                float s0, s1;
                if (m < NN)
                    s0 = ((m == 0) ? sm[OFF_B0 + r]
                                   : sm[OFF_BV + r*24 + gm] + sm[OFF_BH + r*24 + cm])
                         + acc[nt][half*2];
                else s0 = -1e30f;
                if (m1 < NN)
                    s1 = sm[OFF_BV + r*24 + gm1] + sm[OFF_BH + r*24 + cm1] + acc[nt][half*2+1];
                else s1 = -1e30f;
                if (m  < SDIM) sm[OFF_S + r * SS + m]  = s0;
                if (m1 < SDIM) sm[OFF_S + r * SS + m1] = s1;
            }
        }
    }
    __syncthreads();

    // ---------------- Phase C: softmax in place (unnormalized p; 1/sum deferred)
    {
        for (int rr = 0; rr < 4; rr++) {
            int n = wid * 4 + rr;
            float* srow = &sm[OFF_S + n * SS];
            float mx = -1e30f;
            for (int m = lane; m < SDIM; m += 32) mx = fmaxf(mx, srow[m]);
            #pragma unroll
            for (int o = 16; o; o >>= 1) mx = fmaxf(mx, __shfl_xor_sync(0xffffffffu, mx, o));
            float sum = 0.f;
            for (int m = lane; m < SDIM; m += 32) {
                float p = __expf((srow[m] - mx) * SCALEF);
                srow[m] = p;
                sum += p;
            }
            #pragma unroll
            for (int o = 16; o; o >>= 1) sum += __shfl_xor_sync(0xffffffffu, sum, o);
            if (lane == 0) sm[OFF_INV + n] = 1.f / sum;
        }
    }
    __syncthreads();

    // ---------------- Phase D: 24-block row/col sums of p, p0
    {
        for (int rr = 0; rr < 4; rr++) {
            int n = wid * 4 + rr;
            const float* pr = &sm[OFF_S + n * SS];
            if (lane < 24) {
                float rsv = 0.f, csv = 0.f;
                #pragma unroll 4
                for (int k = 0; k < 24; k++) {
                    rsv += pr[1 + 24 * lane + k];
                    csv += pr[1 + 24 * k + lane];
                }
                sm[OFF_RS + n * 24 + lane] = rsv;
                sm[OFF_CS + n * 24 + lane] = csv;
            } else if (lane == 24) {
                sm[OFF_P0 + n] = pr[0];
            }
        }
    }

    // ---------------- Phase E: O = P V via mma.sync tf32 (full O in regs across chunks)
    {
        const int D0 = colblk * 16;
        float acc[2][4] = {{0,0,0,0},{0,0,0,0}};
        for (int chunk = 0; chunk < 5; chunk++) {
            __syncthreads();   // first iter also fences Phase-D writes; KS dead -> VT reuse
            for (int idx = tid; idx < 128 * 16; idx += NT) {
                int mm = idx >> 4, d4 = idx & 15;
                int m = chunk * 128 + mm;
                float4 f = make_float4(0.f, 0.f, 0.f, 0.f);
                if (m < NN)
                    f = *(const float4*)&x[((size_t)(b * NN + m)) * XS + 1536 + h * 64 + d4 * 4];
                *(float4*)&sm[OFF_VT + mm * VSS + d4 * 4] =
                    make_float4(f.x * w, f.y * w, f.z * w, f.w * w);
            }
            __syncthreads();

            int kmax = (chunk == 4) ? 12 : 16;   // chunk 4 covers m 512..607 only
            const float* pA = &sm[OFF_S + (R0 + ly) * SS + chunk * 128 + lx];
            for (int k8 = 0; k8 < kmax; k8++) {
                int kc = k8 * 8;
                uint32_t ah0, ah1, ah2, ah3, al0, al1, al2, al3;
                split_tf32(pA[kc],           ah0, al0);
                split_tf32(pA[8*SS + kc],    ah1, al1);
                split_tf32(pA[kc + 4],       ah2, al2);
                split_tf32(pA[8*SS + kc + 4],ah3, al3);
                #pragma unroll
                for (int nt = 0; nt < 2; nt++) {
                    const float* bp = &sm[OFF_VT + (kc + lx) * VSS + D0 + nt * 8 + ly];
                    uint32_t bh0, bh1, bl0, bl1;
                    split_tf32(bp[0],       bh0, bl0);
                    split_tf32(bp[4 * VSS], bh1, bl1);
                    mma_tf32(acc[nt], ah0, ah1, ah2, ah3, bh0, bh1);
                    mma_tf32(acc[nt], al0, al1, al2, al3, bh0, bh1);
                    mma_tf32(acc[nt], ah0, ah1, ah2, ah3, bl0, bl1);
                }
            }
        }
        __syncthreads();   // all reads of VT done before PART overwrite
        #pragma unroll
        for (int nt = 0; nt < 2; nt++) {
            #pragma unroll
            for (int half = 0; half < 2; half++) {
                int r = R0 + ly + half * 8;
                *(float2*)&sm[OFF_PART + r * 64 + D0 + nt * 8 + lx * 2] =
                    make_float2(acc[nt][half*2], acc[nt][half*2+1]);
            }
        }
    }
    __syncthreads();

    // ---------------- Epilogue: add rel-v (49 rank-1 terms), normalize, store
    {
        int n  = tid >> 3;
        int d0 = (tid & 7) * 8;
        float o[8];
        #pragma unroll
        for (int dd = 0; dd < 8; dd++)
            o[dd] = sm[OFF_PART + n * 64 + d0 + dd];

        int qn = n0 + n;
        bool zi = (qn == 0) || (qn >= NN);
        int gq = 0, cq = 0;
        if (!zi) { gq = (qn - 1) / 24; cq = (qn - 1) % 24; }

        {
            float c0 = sm[OFF_P0 + n];
            float4 a  = __ldg((const float4*)&tvv[d0]);
            float4 a2 = __ldg((const float4*)&tvv[d0 + 4]);
            float4 bb = __ldg((const float4*)&tvh[d0]);
            float4 b2 = __ldg((const float4*)&tvh[d0 + 4]);
            o[0] += c0 * (a.x + bb.x); o[1] += c0 * (a.y + bb.y);
            o[2] += c0 * (a.z + bb.z); o[3] += c0 * (a.w + bb.w);
            o[4] += c0 * (a2.x + b2.x); o[5] += c0 * (a2.y + b2.y);
            o[6] += c0 * (a2.z + b2.z); o[7] += c0 * (a2.w + b2.w);
        }
        #pragma unroll 4
        for (int g = 0; g < 24; g++) {
            int t = zi ? 0 : clip14(g - gq);
            float coef = sm[OFF_RS + n * 24 + g];
            const float* tr = &tvv[t * 64 + d0];
            float4 a  = __ldg((const float4*)tr);
            float4 a2 = __ldg((const float4*)(tr + 4));
            o[0] += coef * a.x;  o[1] += coef * a.y;  o[2] += coef * a.z;  o[3] += coef * a.w;
            o[4] += coef * a2.x; o[5] += coef * a2.y; o[6] += coef * a2.z; o[7] += coef * a2.w;
        }
        #pragma unroll 4
        for (int c = 0; c < 24; c++) {
            int t = zi ? 0 : clip14(c - cq);
            float coef = sm[OFF_CS + n * 24 + c];
            const float* tr = &tvh[t * 64 + d0];
            float4 a  = __ldg((const float4*)tr);
            float4 a2 = __ldg((const float4*)(tr + 4));
            o[0] += coef * a.x;  o[1] += coef * a.y;  o[2] += coef * a.z;  o[3] += coef * a.w;
            o[4] += coef * a2.x; o[5] += coef * a2.y; o[6] += coef * a2.z; o[7] += coef * a2.w;
        }

        float invs = sm[OFF_INV + n];
        if (qn < NN) {
            float* op = &out[((size_t)(b * NN + qn)) * OS + h * 64 + d0];
            *(float4*)op       = make_float4(o[0] * invs, o[1] * invs, o[2] * invs, o[3] * invs);
            *(float4*)(op + 4) = make_float4(o[4] * invs, o[5] * invs, o[6] * invs, o[7] * invs);
        }
    }
}

extern "C" void kernel_launch(void* const* d_in, const int* in_sizes, int n_in,
                              void* d_out, int out_size) {
    const float* x   = (const float*)d_in[0];
    const float* wts = (const float*)d_in[1];
    const float* tkv = (const float*)d_in[2];
    const float* tkh = (const float*)d_in[3];
    const float* tvv = (const float*)d_in[4];
    const float* tvh = (const float*)d_in[5];
    float* out = (float*)d_out;

    size_t smem = SMEM_FLOATS * sizeof(float);   // 224,000 B
    cudaFuncSetAttribute(attn_kernel, cudaFuncAttributeMaxDynamicSharedMemorySize, (int)smem);
    dim3 grid((NN + TQ - 1) / TQ, HH, BB);       // (10, 12, 16)
    attn_kernel<<<grid, NT, smem>>>(x, wts, tkv, tkh, tvv, tvh, out);
    (void)in_sizes; (void)n_in; (void)out_size;
}